// round 1
// baseline (speedup 1.0000x reference)
#include <cuda_runtime.h>

#define NN 100000
#define EE 600000
#define HH 128
#define ZZ 64
#define BIN 198

// ---------------- device scratch (no allocations allowed) ----------------
__device__ int   g_i64;                 // 1 if edges are int64, 0 if int32
__device__ int   g_counts[NN];
__device__ int   g_off[NN + 1];
__device__ int   g_cursor[NN];
__device__ int   g_csr[EE];             // src indices grouped by dst
__device__ float g_feat[(size_t)NN * HH];
__device__ float g_t[(size_t)NN * 256]; // per-layer [N,256]: cols 0-127 = x@Ws, 128-255 = x@Wn

// ---------------- small helpers ----------------
__device__ __forceinline__ unsigned long long pack2(float x, float y) {
    unsigned long long d;
    asm("mov.b64 %0, {%1, %2};" : "=l"(d) : "f"(x), "f"(y));
    return d;
}
__device__ __forceinline__ unsigned long long fma2(unsigned long long a,
                                                   unsigned long long b,
                                                   unsigned long long c) {
    unsigned long long d;
    asm("fma.rn.f32x2 %0, %1, %2, %3;" : "=l"(d) : "l"(a), "l"(b), "l"(c));
    return d;
}
__device__ __forceinline__ int edge_val(const void* edges, long long idx) {
    if (g_i64) return (int)((const long long*)edges)[idx];
    return ((const int*)edges)[idx];
}

// ---------------- CSR construction ----------------
__global__ void detect_kernel(const void* edges) {
    if (threadIdx.x == 0 && blockIdx.x == 0) {
        const long long* p = (const long long*)edges;
        bool ok = true;
        for (int i = 0; i < 64; i++) {
            long long v = p[i];
            if (v < 0 || v >= NN) { ok = false; break; }
        }
        g_i64 = ok ? 1 : 0;
    }
}

__global__ void zero_counts_kernel() {
    int i = blockIdx.x * blockDim.x + threadIdx.x;
    if (i < NN) g_counts[i] = 0;
}

__global__ void count_kernel(const void* edges) {
    int e = blockIdx.x * blockDim.x + threadIdx.x;
    if (e < EE) {
        int dst = edge_val(edges, 2LL * e + 1);
        atomicAdd(&g_counts[dst], 1);
    }
}

// single-block scan: 1024 threads, each owns a contiguous chunk
__global__ void scan_kernel() {
    __shared__ int sums[1024];
    const int C = (NN + 1023) / 1024;   // 98
    int t = threadIdx.x;
    int base = t * C;
    int s = 0;
    for (int j = 0; j < C; j++) {
        int idx = base + j;
        if (idx < NN) s += g_counts[idx];
    }
    sums[t] = s;
    __syncthreads();
    for (int d = 1; d < 1024; d <<= 1) {
        int v = (t >= d) ? sums[t - d] : 0;
        __syncthreads();
        sums[t] += v;
        __syncthreads();
    }
    int run = (t == 0) ? 0 : sums[t - 1];
    for (int j = 0; j < C; j++) {
        int idx = base + j;
        if (idx < NN) {
            g_off[idx] = run;
            g_cursor[idx] = run;
            run += g_counts[idx];
        }
    }
    if (t == 1023) g_off[NN] = sums[1023];
}

__global__ void scatter_kernel(const void* edges) {
    int e = blockIdx.x * blockDim.x + threadIdx.x;
    if (e < EE) {
        int src = edge_val(edges, 2LL * e);
        int dst = edge_val(edges, 2LL * e + 1);
        int p = atomicAdd(&g_cursor[dst], 1);
        g_csr[p] = src;
    }
}

// ---------------- layer 0 GEMM: [N,6] x [6,256] -> g_t ----------------
__global__ void l0_gemm_kernel(const float* __restrict__ vert,
                               const float* __restrict__ vpot,
                               const float* __restrict__ W0s,
                               const float* __restrict__ W0n) {
    int n = blockIdx.x;
    int c = threadIdx.x;     // 0..255
    __shared__ float xi[6];
    if (c < 6) xi[c] = (c < 3) ? vert[n * 3 + c] : vpot[n * 3 + (c - 3)];
    __syncthreads();
    const float* B = (c < 128) ? (W0s + c) : (W0n + (c - 128));
    float acc = 0.f;
#pragma unroll
    for (int k = 0; k < 6; k++) acc += xi[k] * B[k * HH];
    g_t[(size_t)n * 256 + c] = acc;
}

// ---------------- body GEMM: A=[feat|z_i|in6] (N x 198), B=Ws or Wn (198x128) ----------------
__global__ void __launch_bounds__(256)
body_gemm_kernel(const float* __restrict__ zi,
                 const float* __restrict__ vert,
                 const float* __restrict__ vpot,
                 const float* __restrict__ Ws,
                 const float* __restrict__ Wn) {
    const float* W = blockIdx.y ? Wn : Ws;
    const int colbase = blockIdx.y * 128;
    const int row0 = blockIdx.x * 128;

    __shared__ float As[16][132];   // padded to reduce store conflicts
    __shared__ float Bs[16][128];

    int tid = threadIdx.x;
    int tx = tid & 15;
    int ty = tid >> 4;

    unsigned long long acc[8][4];
#pragma unroll
    for (int i = 0; i < 8; i++)
#pragma unroll
        for (int j = 0; j < 4; j++) acc[i][j] = 0ull;

    for (int kt = 0; kt < 13; kt++) {        // 13 * 16 = 208 >= 198
        int kbase = kt * 16;
        // --- load A tile (with concat decode) ---
#pragma unroll
        for (int j = 0; j < 8; j++) {
            int l = tid + j * 256;
            int m = l >> 4;
            int kk = l & 15;
            int n = row0 + m;
            int k = kbase + kk;
            float v = 0.f;
            if (n < NN) {
                if (k < 128)       v = g_feat[(size_t)n * 128 + k];
                else if (k < 192)  v = zi[(size_t)n * 64 + (k - 128)];
                else if (k < 195)  v = vert[n * 3 + (k - 192)];
                else if (k < 198)  v = vpot[n * 3 + (k - 195)];
            }
            As[kk][m] = v;
        }
        // --- load B tile ---
#pragma unroll
        for (int j = 0; j < 8; j++) {
            int l = tid + j * 256;
            int c = l & 127;
            int kk = l >> 7;
            int k = kbase + kk;
            Bs[kk][c] = (k < BIN) ? W[k * 128 + c] : 0.f;
        }
        __syncthreads();
        // --- compute ---
#pragma unroll
        for (int kk = 0; kk < 16; kk++) {
            float4 a0 = *(const float4*)&As[kk][ty * 8];
            float4 a1 = *(const float4*)&As[kk][ty * 8 + 4];
            ulonglong2 b0 = *(const ulonglong2*)&Bs[kk][tx * 8];
            ulonglong2 b1 = *(const ulonglong2*)&Bs[kk][tx * 8 + 4];
            unsigned long long ad[8];
            ad[0] = pack2(a0.x, a0.x); ad[1] = pack2(a0.y, a0.y);
            ad[2] = pack2(a0.z, a0.z); ad[3] = pack2(a0.w, a0.w);
            ad[4] = pack2(a1.x, a1.x); ad[5] = pack2(a1.y, a1.y);
            ad[6] = pack2(a1.z, a1.z); ad[7] = pack2(a1.w, a1.w);
#pragma unroll
            for (int i = 0; i < 8; i++) {
                acc[i][0] = fma2(ad[i], b0.x, acc[i][0]);
                acc[i][1] = fma2(ad[i], b0.y, acc[i][1]);
                acc[i][2] = fma2(ad[i], b1.x, acc[i][2]);
                acc[i][3] = fma2(ad[i], b1.y, acc[i][3]);
            }
        }
        __syncthreads();
    }
    // --- epilogue: packed f32x2 accumulators store directly as 8B ---
#pragma unroll
    for (int i = 0; i < 8; i++) {
        int n = row0 + ty * 8 + i;
        if (n < NN) {
            unsigned long long* dst =
                (unsigned long long*)(g_t + (size_t)n * 256 + colbase + tx * 8);
            dst[0] = acc[i][0];
            dst[1] = acc[i][1];
            dst[2] = acc[i][2];
            dst[3] = acc[i][3];
        }
    }
}

// ---------------- aggregation + bias + relu: one warp per node ----------------
__global__ void combine_relu_kernel(const float* __restrict__ bias) {
    int gw = (blockIdx.x * blockDim.x + threadIdx.x) >> 5;
    int lane = threadIdx.x & 31;
    if (gw >= NN) return;
    int n = gw;
    int s0 = g_off[n], s1 = g_off[n + 1];
    float4 acc = make_float4(0.f, 0.f, 0.f, 0.f);
    for (int e = s0; e < s1; e++) {
        int s = g_csr[e];
        float4 v = *((const float4*)(g_t + (size_t)s * 256 + 128) + lane);
        acc.x += v.x; acc.y += v.y; acc.z += v.z; acc.w += v.w;
    }
    float inv = 1.0f / (float)max(s1 - s0, 1);
    float4 ts = *((const float4*)(g_t + (size_t)n * 256) + lane);
    float4 b4 = ((const float4*)bias)[lane];
    float4 o;
    o.x = fmaxf(ts.x + acc.x * inv + b4.x, 0.f);
    o.y = fmaxf(ts.y + acc.y * inv + b4.y, 0.f);
    o.z = fmaxf(ts.z + acc.z * inv + b4.z, 0.f);
    o.w = fmaxf(ts.w + acc.w * inv + b4.w, 0.f);
    *((float4*)(g_feat + (size_t)n * HH) + lane) = o;
}

// ---------------- final GEMM: feat[N,128] x [Wls|Wln] (128x6) -> g_t as [N,6] ----------------
__global__ void final_gemm_kernel(const float* __restrict__ Wls,
                                  const float* __restrict__ Wln) {
    __shared__ float B[128][6];
    int tid = threadIdx.x;
    for (int i = tid; i < 128 * 6; i += 256) {
        int k = i / 6, c = i % 6;
        B[k][c] = (c < 3) ? Wls[k * 3 + c] : Wln[k * 3 + (c - 3)];
    }
    __syncthreads();
    int gw = (blockIdx.x * 256 + tid) >> 5;
    int lane = tid & 31;
    if (gw >= NN) return;
    int n = gw;
    float p0 = 0.f, p1 = 0.f, p2 = 0.f, p3 = 0.f, p4 = 0.f, p5 = 0.f;
    for (int k = lane; k < 128; k += 32) {
        float f = g_feat[(size_t)n * 128 + k];
        p0 += f * B[k][0]; p1 += f * B[k][1]; p2 += f * B[k][2];
        p3 += f * B[k][3]; p4 += f * B[k][4]; p5 += f * B[k][5];
    }
#pragma unroll
    for (int o = 16; o > 0; o >>= 1) {
        p0 += __shfl_xor_sync(0xffffffff, p0, o);
        p1 += __shfl_xor_sync(0xffffffff, p1, o);
        p2 += __shfl_xor_sync(0xffffffff, p2, o);
        p3 += __shfl_xor_sync(0xffffffff, p3, o);
        p4 += __shfl_xor_sync(0xffffffff, p4, o);
        p5 += __shfl_xor_sync(0xffffffff, p5, o);
    }
    if (lane == 0) {
        g_t[(size_t)n * 6 + 0] = p0;
        g_t[(size_t)n * 6 + 1] = p1;
        g_t[(size_t)n * 6 + 2] = p2;
        g_t[(size_t)n * 6 + 3] = p3;
        g_t[(size_t)n * 6 + 4] = p4;
        g_t[(size_t)n * 6 + 5] = p5;
    }
}

// ---------------- final combine: out = t_s + agg(t_n)/deg + bl (no relu) ----------------
__global__ void final_combine_kernel(const float* __restrict__ bl,
                                     float* __restrict__ out) {
    int n = blockIdx.x * blockDim.x + threadIdx.x;
    if (n >= NN) return;
    int s0 = g_off[n], s1 = g_off[n + 1];
    float a0 = 0.f, a1 = 0.f, a2 = 0.f;
    for (int e = s0; e < s1; e++) {
        int s = g_csr[e];
        a0 += g_t[(size_t)s * 6 + 3];
        a1 += g_t[(size_t)s * 6 + 4];
        a2 += g_t[(size_t)s * 6 + 5];
    }
    float inv = 1.0f / (float)max(s1 - s0, 1);
    out[n * 3 + 0] = g_t[(size_t)n * 6 + 0] + a0 * inv + bl[0];
    out[n * 3 + 1] = g_t[(size_t)n * 6 + 1] + a1 * inv + bl[1];
    out[n * 3 + 2] = g_t[(size_t)n * 6 + 2] + a2 * inv + bl[2];
}

// ---------------- launch ----------------
extern "C" void kernel_launch(void* const* d_in, const int* in_sizes, int n_in,
                              void* d_out, int out_size) {
    const float* vert = (const float*)d_in[0];
    const void*  edges = d_in[1];
    const float* vpot = (const float*)d_in[2];
    const float* z    = (const float*)d_in[3];
    const float* W0s  = (const float*)d_in[4];
    const float* W0n  = (const float*)d_in[5];
    const float* b0   = (const float*)d_in[6];
    const float* Wbs  = (const float*)d_in[7];
    const float* Wbn  = (const float*)d_in[8];
    const float* bb   = (const float*)d_in[9];
    const float* Wls  = (const float*)d_in[10];
    const float* Wln  = (const float*)d_in[11];
    const float* bl   = (const float*)d_in[12];
    float* out = (float*)d_out;

    // CSR build (every launch; deterministic topology)
    detect_kernel<<<1, 32>>>(edges);
    zero_counts_kernel<<<(NN + 255) / 256, 256>>>();
    count_kernel<<<(EE + 255) / 256, 256>>>(edges);
    scan_kernel<<<1, 1024>>>();
    scatter_kernel<<<(EE + 255) / 256, 256>>>(edges);

    // layer 0
    l0_gemm_kernel<<<NN, 256>>>(vert, vpot, W0s, W0n);
    combine_relu_kernel<<<(NN * 32 + 255) / 256, 256>>>(b0);

    // 4 body layers
    for (int i = 0; i < 4; i++) {
        body_gemm_kernel<<<dim3((NN + 127) / 128, 2), 256>>>(
            z + (size_t)i * NN * ZZ, vert, vpot,
            Wbs + (size_t)i * BIN * HH, Wbn + (size_t)i * BIN * HH);
        combine_relu_kernel<<<(NN * 32 + 255) / 256, 256>>>(bb + i * HH);
    }

    // head
    final_gemm_kernel<<<(NN * 32 + 255) / 256, 256>>>(Wls, Wln);
    final_combine_kernel<<<(NN + 255) / 256, 256>>>(bl, out);
}

// round 2
// speedup vs baseline: 1.6847x; 1.6847x over previous
#include <cuda_runtime.h>

#define NN 100000
#define EE 600000
#define HH 128
#define ZZ 64
#define BIN 198
#define SCAN_BLOCKS ((NN + 1023) / 1024)   // 98

// ---------------- device scratch (no allocations allowed) ----------------
__device__ int   g_i64;                 // 1 if edges are int64, 0 if int32
__device__ int   g_counts[NN];
__device__ int   g_off[NN + 1];
__device__ int   g_cursor[NN];
__device__ int   g_csr[EE];             // src indices grouped by dst
__device__ int   g_bsums[SCAN_BLOCKS];
__device__ int   g_bsum_ex[SCAN_BLOCKS];
__device__ float g_feat[(size_t)NN * HH];
__device__ float g_t[(size_t)NN * 256]; // per-layer [N,256]: cols 0-127 = x@Ws, 128-255 = x@Wn

// ---------------- small helpers ----------------
__device__ __forceinline__ unsigned long long pack2(float x, float y) {
    unsigned long long d;
    asm("mov.b64 %0, {%1, %2};" : "=l"(d) : "f"(x), "f"(y));
    return d;
}
__device__ __forceinline__ unsigned long long fma2(unsigned long long a,
                                                   unsigned long long b,
                                                   unsigned long long c) {
    unsigned long long d;
    asm("fma.rn.f32x2 %0, %1, %2, %3;" : "=l"(d) : "l"(a), "l"(b), "l"(c));
    return d;
}
__device__ __forceinline__ int edge_val(const void* edges, long long idx) {
    if (g_i64) return (int)((const long long*)edges)[idx];
    return ((const int*)edges)[idx];
}

// ---------------- int64/int32 edge detection (one warp, parallel) ----------------
__global__ void detect_kernel(const void* edges) {
    const long long* p = (const long long*)edges;
    int lane = threadIdx.x;
    long long v = p[lane];                 // 32 parallel loads
    bool ok = (v >= 0 && v < NN);
    unsigned m = __ballot_sync(0xffffffff, ok);
    if (lane == 0) g_i64 = (m == 0xffffffffu) ? 1 : 0;
}

__global__ void zero_counts_kernel() {
    int i = blockIdx.x * blockDim.x + threadIdx.x;
    if (i < NN) g_counts[i] = 0;
}

__global__ void count_kernel(const void* edges) {
    int e = blockIdx.x * blockDim.x + threadIdx.x;
    if (e < EE) {
        int dst = edge_val(edges, 2LL * e + 1);
        atomicAdd(&g_counts[dst], 1);
    }
}

// ---------------- multi-block scan ----------------
__global__ void scan_block_kernel() {
    __shared__ int s[1024];
    int t = threadIdx.x;
    int i = blockIdx.x * 1024 + t;
    int v = (i < NN) ? g_counts[i] : 0;
    s[t] = v;
    __syncthreads();
#pragma unroll
    for (int d = 1; d < 1024; d <<= 1) {
        int x = (t >= d) ? s[t - d] : 0;
        __syncthreads();
        s[t] += x;
        __syncthreads();
    }
    if (i < NN) g_off[i] = s[t] - v;      // exclusive within block
    if (t == 1023) g_bsums[blockIdx.x] = s[1023];
}

__global__ void scan_tops_kernel() {
    __shared__ int s[128];
    int t = threadIdx.x;
    int v = (t < SCAN_BLOCKS) ? g_bsums[t] : 0;
    s[t] = v;
    __syncthreads();
#pragma unroll
    for (int d = 1; d < 128; d <<= 1) {
        int x = (t >= d) ? s[t - d] : 0;
        __syncthreads();
        s[t] += x;
        __syncthreads();
    }
    if (t < SCAN_BLOCKS) g_bsum_ex[t] = s[t] - v;
}

__global__ void scan_add_kernel() {
    int t = threadIdx.x;
    int i = blockIdx.x * 1024 + t;
    if (i < NN) {
        int o = g_off[i] + g_bsum_ex[blockIdx.x];
        g_off[i] = o;
        g_cursor[i] = o;
    }
    if (i == 0) g_off[NN] = EE;
}

__global__ void scatter_kernel(const void* edges) {
    int e = blockIdx.x * blockDim.x + threadIdx.x;
    if (e < EE) {
        int src = edge_val(edges, 2LL * e);
        int dst = edge_val(edges, 2LL * e + 1);
        int p = atomicAdd(&g_cursor[dst], 1);
        g_csr[p] = src;
    }
}

// ---------------- layer 0 GEMM: [N,6] x [6,256] -> g_t ----------------
__global__ void l0_gemm_kernel(const float* __restrict__ vert,
                               const float* __restrict__ vpot,
                               const float* __restrict__ W0s,
                               const float* __restrict__ W0n) {
    int n = blockIdx.x;
    int c = threadIdx.x;     // 0..255
    __shared__ float xi[6];
    if (c < 6) xi[c] = (c < 3) ? vert[n * 3 + c] : vpot[n * 3 + (c - 3)];
    __syncthreads();
    const float* B = (c < 128) ? (W0s + c) : (W0n + (c - 128));
    float acc = 0.f;
#pragma unroll
    for (int k = 0; k < 6; k++) acc += xi[k] * B[k * HH];
    g_t[(size_t)n * 256 + c] = acc;
}

// ---------------- body GEMM: A=[feat|z_i|in6] (N x 198), B=Ws or Wn (198x128) ----
// double-buffered smem, f32x2 FMA, conflict-free B reads (4+4 col split)
__global__ void __launch_bounds__(256)
body_gemm_kernel(const float* __restrict__ zi,
                 const float* __restrict__ vert,
                 const float* __restrict__ vpot,
                 const float* __restrict__ Ws,
                 const float* __restrict__ Wn) {
    const float* W = blockIdx.y ? Wn : Ws;
    const int colbase = blockIdx.y * 128;
    const int row0 = blockIdx.x * 128;

    __shared__ float As[2][16][132];   // [stage][k][m], m padded
    __shared__ float Bs[2][16][128];   // [stage][k][c]

    const int tid = threadIdx.x;
    const int tx = tid & 15;           // 16 col-groups
    const int ty = tid >> 4;           // 16 row-groups

    unsigned long long acc[8][4];
#pragma unroll
    for (int i = 0; i < 8; i++)
#pragma unroll
        for (int j = 0; j < 4; j++) acc[i][j] = 0ull;

    float ra[8], rb[8];

    // ---- global -> regs loaders ----
    auto loadA = [&](int kt, float* r) {
        int kbase = kt * 16;
#pragma unroll
        for (int j = 0; j < 8; j++) {
            int l = tid + j * 256;
            int m = l >> 4;
            int kk = l & 15;
            int n = row0 + m;
            int k = kbase + kk;
            float v = 0.f;
            if (n < NN) {
                if (k < 128)       v = g_feat[(size_t)n * 128 + k];
                else if (k < 192)  v = zi[(size_t)n * 64 + (k - 128)];
                else if (k < 195)  v = vert[n * 3 + (k - 192)];
                else if (k < 198)  v = vpot[n * 3 + (k - 195)];
            }
            r[j] = v;
        }
    };
    auto loadB = [&](int kt, float* r) {
        int kbase = kt * 16;
#pragma unroll
        for (int j = 0; j < 8; j++) {
            int l = tid + j * 256;
            int c = l & 127;
            int kk = l >> 7;
            int k = kbase + kk + j * 0;
            k = kbase + (l >> 7);
            r[j] = (k < BIN) ? W[k * 128 + c] : 0.f;
        }
    };
    auto storeA = [&](int st, const float* r) {
#pragma unroll
        for (int j = 0; j < 8; j++) {
            int l = tid + j * 256;
            As[st][l & 15][l >> 4] = r[j];
        }
    };
    auto storeB = [&](int st, const float* r) {
#pragma unroll
        for (int j = 0; j < 8; j++) {
            int l = tid + j * 256;
            Bs[st][l >> 7][l & 127] = r[j];
        }
    };

    loadA(0, ra);
    loadB(0, rb);
    storeA(0, ra);
    storeB(0, rb);
    __syncthreads();

    for (int kt = 0; kt < 13; kt++) {     // 13 * 16 = 208 >= 198
        int cur = kt & 1;
        if (kt < 12) { loadA(kt + 1, ra); loadB(kt + 1, rb); }
#pragma unroll
        for (int kk = 0; kk < 16; kk++) {
            float4 a0 = *(const float4*)&As[cur][kk][ty * 8];
            float4 a1 = *(const float4*)&As[cur][kk][ty * 8 + 4];
            // conflict-free B: 16B-strided within each half
            ulonglong2 b0 = *(const ulonglong2*)&Bs[cur][kk][tx * 4];
            ulonglong2 b1 = *(const ulonglong2*)&Bs[cur][kk][64 + tx * 4];
            unsigned long long ad[8];
            ad[0] = pack2(a0.x, a0.x); ad[1] = pack2(a0.y, a0.y);
            ad[2] = pack2(a0.z, a0.z); ad[3] = pack2(a0.w, a0.w);
            ad[4] = pack2(a1.x, a1.x); ad[5] = pack2(a1.y, a1.y);
            ad[6] = pack2(a1.z, a1.z); ad[7] = pack2(a1.w, a1.w);
#pragma unroll
            for (int i = 0; i < 8; i++) {
                acc[i][0] = fma2(ad[i], b0.x, acc[i][0]);
                acc[i][1] = fma2(ad[i], b0.y, acc[i][1]);
                acc[i][2] = fma2(ad[i], b1.x, acc[i][2]);
                acc[i][3] = fma2(ad[i], b1.y, acc[i][3]);
            }
        }
        if (kt < 12) { storeA(cur ^ 1, ra); storeB(cur ^ 1, rb); }
        __syncthreads();
    }

    // epilogue: cols [colbase + tx*4, +4) and [colbase + 64 + tx*4, +4)
#pragma unroll
    for (int i = 0; i < 8; i++) {
        int n = row0 + ty * 8 + i;
        if (n < NN) {
            float* base = g_t + (size_t)n * 256 + colbase;
            ulonglong2 v0; v0.x = acc[i][0]; v0.y = acc[i][1];
            ulonglong2 v1; v1.x = acc[i][2]; v1.y = acc[i][3];
            *(ulonglong2*)(base + tx * 4) = v0;
            *(ulonglong2*)(base + 64 + tx * 4) = v1;
        }
    }
}

// ---------------- aggregation + bias + relu: one warp per node ----------------
__global__ void combine_relu_kernel(const float* __restrict__ bias) {
    int gw = (blockIdx.x * blockDim.x + threadIdx.x) >> 5;
    int lane = threadIdx.x & 31;
    if (gw >= NN) return;
    int n = gw;
    int s0 = g_off[n], s1 = g_off[n + 1];
    float4 acc = make_float4(0.f, 0.f, 0.f, 0.f);
    for (int e = s0; e < s1; e++) {
        int s = g_csr[e];
        float4 v = *((const float4*)(g_t + (size_t)s * 256 + 128) + lane);
        acc.x += v.x; acc.y += v.y; acc.z += v.z; acc.w += v.w;
    }
    float inv = 1.0f / (float)max(s1 - s0, 1);
    float4 ts = *((const float4*)(g_t + (size_t)n * 256) + lane);
    float4 b4 = ((const float4*)bias)[lane];
    float4 o;
    o.x = fmaxf(ts.x + acc.x * inv + b4.x, 0.f);
    o.y = fmaxf(ts.y + acc.y * inv + b4.y, 0.f);
    o.z = fmaxf(ts.z + acc.z * inv + b4.z, 0.f);
    o.w = fmaxf(ts.w + acc.w * inv + b4.w, 0.f);
    *((float4*)(g_feat + (size_t)n * HH) + lane) = o;
}

// ---------------- final GEMM: feat[N,128] x [Wls|Wln] (128x6) -> g_t as [N,6] ----
__global__ void final_gemm_kernel(const float* __restrict__ Wls,
                                  const float* __restrict__ Wln) {
    __shared__ float B[128][6];
    int tid = threadIdx.x;
    for (int i = tid; i < 128 * 6; i += 256) {
        int k = i / 6, c = i % 6;
        B[k][c] = (c < 3) ? Wls[k * 3 + c] : Wln[k * 3 + (c - 3)];
    }
    __syncthreads();
    int gw = (blockIdx.x * 256 + tid) >> 5;
    int lane = tid & 31;
    if (gw >= NN) return;
    int n = gw;
    float p0 = 0.f, p1 = 0.f, p2 = 0.f, p3 = 0.f, p4 = 0.f, p5 = 0.f;
    for (int k = lane; k < 128; k += 32) {
        float f = g_feat[(size_t)n * 128 + k];
        p0 += f * B[k][0]; p1 += f * B[k][1]; p2 += f * B[k][2];
        p3 += f * B[k][3]; p4 += f * B[k][4]; p5 += f * B[k][5];
    }
#pragma unroll
    for (int o = 16; o > 0; o >>= 1) {
        p0 += __shfl_xor_sync(0xffffffff, p0, o);
        p1 += __shfl_xor_sync(0xffffffff, p1, o);
        p2 += __shfl_xor_sync(0xffffffff, p2, o);
        p3 += __shfl_xor_sync(0xffffffff, p3, o);
        p4 += __shfl_xor_sync(0xffffffff, p4, o);
        p5 += __shfl_xor_sync(0xffffffff, p5, o);
    }
    if (lane == 0) {
        g_t[(size_t)n * 6 + 0] = p0;
        g_t[(size_t)n * 6 + 1] = p1;
        g_t[(size_t)n * 6 + 2] = p2;
        g_t[(size_t)n * 6 + 3] = p3;
        g_t[(size_t)n * 6 + 4] = p4;
        g_t[(size_t)n * 6 + 5] = p5;
    }
}

// ---------------- final combine: out = t_s + agg(t_n)/deg + bl (no relu) --------
__global__ void final_combine_kernel(const float* __restrict__ bl,
                                     float* __restrict__ out) {
    int n = blockIdx.x * blockDim.x + threadIdx.x;
    if (n >= NN) return;
    int s0 = g_off[n], s1 = g_off[n + 1];
    float a0 = 0.f, a1 = 0.f, a2 = 0.f;
    for (int e = s0; e < s1; e++) {
        int s = g_csr[e];
        a0 += g_t[(size_t)s * 6 + 3];
        a1 += g_t[(size_t)s * 6 + 4];
        a2 += g_t[(size_t)s * 6 + 5];
    }
    float inv = 1.0f / (float)max(s1 - s0, 1);
    out[n * 3 + 0] = g_t[(size_t)n * 6 + 0] + a0 * inv + bl[0];
    out[n * 3 + 1] = g_t[(size_t)n * 6 + 1] + a1 * inv + bl[1];
    out[n * 3 + 2] = g_t[(size_t)n * 6 + 2] + a2 * inv + bl[2];
}

// ---------------- launch ----------------
extern "C" void kernel_launch(void* const* d_in, const int* in_sizes, int n_in,
                              void* d_out, int out_size) {
    const float* vert = (const float*)d_in[0];
    const void*  edges = d_in[1];
    const float* vpot = (const float*)d_in[2];
    const float* z    = (const float*)d_in[3];
    const float* W0s  = (const float*)d_in[4];
    const float* W0n  = (const float*)d_in[5];
    const float* b0   = (const float*)d_in[6];
    const float* Wbs  = (const float*)d_in[7];
    const float* Wbn  = (const float*)d_in[8];
    const float* bb   = (const float*)d_in[9];
    const float* Wls  = (const float*)d_in[10];
    const float* Wln  = (const float*)d_in[11];
    const float* bl   = (const float*)d_in[12];
    float* out = (float*)d_out;

    // CSR build (every launch; deterministic topology)
    detect_kernel<<<1, 32>>>(edges);
    zero_counts_kernel<<<(NN + 1023) / 1024, 1024>>>();
    count_kernel<<<(EE + 255) / 256, 256>>>(edges);
    scan_block_kernel<<<SCAN_BLOCKS, 1024>>>();
    scan_tops_kernel<<<1, 128>>>();
    scan_add_kernel<<<SCAN_BLOCKS, 1024>>>();
    scatter_kernel<<<(EE + 255) / 256, 256>>>(edges);

    // layer 0
    l0_gemm_kernel<<<NN, 256>>>(vert, vpot, W0s, W0n);
    combine_relu_kernel<<<(NN * 32 + 255) / 256, 256>>>(b0);

    // 4 body layers
    for (int i = 0; i < 4; i++) {
        body_gemm_kernel<<<dim3((NN + 127) / 128, 2), 256>>>(
            z + (size_t)i * NN * ZZ, vert, vpot,
            Wbs + (size_t)i * BIN * HH, Wbn + (size_t)i * BIN * HH);
        combine_relu_kernel<<<(NN * 32 + 255) / 256, 256>>>(bb + i * HH);
    }

    // head
    final_gemm_kernel<<<(NN * 32 + 255) / 256, 256>>>(Wls, Wln);
    final_combine_kernel<<<(NN + 255) / 256, 256>>>(bl, out);
}

// round 4
// speedup vs baseline: 2.7721x; 1.6454x over previous
#include <cuda_runtime.h>
#include <cuda_bf16.h>
#include <cstdint>

#define NN 100000
#define EE 600000
#define HH 128
#define ZZ 64
#define BIN 198
#define SCAN_BLOCKS ((NN + 1023) / 1024)   // 98
#define MTILES ((NN + 127) / 128)          // 782

// ---------------- device scratch (no allocations allowed) ----------------
__device__ int   g_i64;
__device__ int   g_counts[NN];
__device__ int   g_off[NN + 1];
__device__ int   g_cursor[NN];
__device__ int   g_csr[EE];
__device__ int   g_bsums[SCAN_BLOCKS];
__device__ int   g_bsum_ex[SCAN_BLOCKS];
__device__ float g_feat[(size_t)NN * HH];          // fp32 feat (head input only)
__device__ float g_t[(size_t)NN * 256];            // GEMM out: cols 0-127 s-half, 128-255 n-half
__device__ __nv_bfloat16 g_Ahi[(size_t)NN * 256];  // concat A, hi part, K padded to 256
__device__ __nv_bfloat16 g_Alo[(size_t)NN * 256];  // lo part
__device__ __nv_bfloat16 g_Whi[4 * 256 * 256];     // [layer][n(256)][k(256)] transposed weights
__device__ __nv_bfloat16 g_Wlo[4 * 256 * 256];
__device__ float g_Wf[4 * 256 * 256];              // [layer][k(256)][n(256)] fp32 (fallback path)

// ---------------- arch feature gate ----------------
#if defined(__CUDA_ARCH_FEAT_SM103_ALL) || defined(__CUDA_ARCH_FEAT_SM100_ALL) || \
    defined(__CUDA_ARCH_FEAT_SM101_ALL) || defined(__CUDA_ARCH_FEAT_SM110_ALL)
#define TC_OK 1
#else
#define TC_OK 0
#endif

// ---------------- PTX helpers (only referenced when TC_OK) ----------------
__device__ __forceinline__ uint32_t elect_one_pred() {
    uint32_t pred;
    asm volatile("{\n\t.reg .pred p;\n\telect.sync _|p, 0xFFFFFFFF;\n\tselp.b32 %0, 1, 0, p;\n\t}"
                 : "=r"(pred));
    return pred;
}
__device__ __forceinline__ uint32_t smem_to_u32(const void* p) {
    uint32_t a;
    asm("{ .reg .u64 t; cvta.to.shared.u64 t, %1; cvt.u32.u64 %0, t; }" : "=r"(a) : "l"(p));
    return a;
}
#define SMEM_SWIZZLE_128B(x) ((x) ^ (((x) >> 3) & 0x70))

#define TCGEN05_ALLOC(sa, n) \
    asm volatile("tcgen05.alloc.cta_group::1.sync.aligned.shared::cta.b32 [%0], %1;" \
                 :: "r"((uint32_t)(sa)), "r"((uint32_t)(n)) : "memory")
#define TCGEN05_DEALLOC(t, n) \
    asm volatile("tcgen05.dealloc.cta_group::1.sync.aligned.b32 %0, %1;" :: "r"(t), "r"(n))
#define TCGEN05_RELINQ() \
    asm volatile("tcgen05.relinquish_alloc_permit.cta_group::1.sync.aligned;")
#define TCGEN05_COMMIT(mb) \
    asm volatile("tcgen05.commit.cta_group::1.mbarrier::arrive::one.shared::cluster.b64 [%0];" \
                 :: "r"((uint32_t)(mb)) : "memory")
#define TCGEN05_FENCE_AFTER() asm volatile("tcgen05.fence::after_thread_sync;" ::: "memory")
#define TCGEN05_FENCE_BEFORE() asm volatile("tcgen05.fence::before_thread_sync;" ::: "memory")
#define TCGEN05_WAIT_LD() asm volatile("tcgen05.wait::ld.sync.aligned;" ::: "memory")
#define FENCE_ASYNC() asm volatile("fence.proxy.async.shared::cta;" ::: "memory")
#define MBARRIER_INIT(mb, c) \
    asm volatile("mbarrier.init.shared.b64 [%0], %1;" :: "r"((uint32_t)(mb)), "r"((uint32_t)(c)) : "memory")

#define MBARRIER_WAIT_PARITY(mb, ph) do { \
    uint32_t _m = (uint32_t)(mb), _p = (uint32_t)(ph), _d; \
    asm volatile("{\n\t.reg .pred p;\n\t" \
        "mbarrier.try_wait.parity.acquire.cta.shared::cta.b64 p, [%1], %2;\n\t" \
        "selp.b32 %0, 1, 0, p;\n\t}" : "=r"(_d) : "r"(_m), "r"(_p) : "memory"); \
    if (!_d) { \
        asm volatile("{\n\t.reg .pred P1;\n\t" \
            "WL_%=:\n\t" \
            "mbarrier.try_wait.parity.acquire.cta.shared::cta.b64 P1, [%0], %1, 0x989680;\n\t" \
            "@P1 bra.uni WD_%=;\n\tbra.uni WL_%=;\n\tWD_%=:\n\t}" \
            :: "r"(_m), "r"(_p) : "memory"); \
    } \
} while (0)

#define TCGEN05_LD_X32(r, ta) \
    asm volatile("tcgen05.ld.sync.aligned.32x32b.x32.b32 " \
        "{%0, %1, %2, %3, %4, %5, %6, %7, %8, %9, %10, %11, %12, %13, %14, %15, " \
        "%16, %17, %18, %19, %20, %21, %22, %23, %24, %25, %26, %27, %28, %29, %30, %31}, [%32];" \
        : "=r"((r)[0]), "=r"((r)[1]), "=r"((r)[2]), "=r"((r)[3]), "=r"((r)[4]), "=r"((r)[5]), \
          "=r"((r)[6]), "=r"((r)[7]), "=r"((r)[8]), "=r"((r)[9]), "=r"((r)[10]), "=r"((r)[11]), \
          "=r"((r)[12]), "=r"((r)[13]), "=r"((r)[14]), "=r"((r)[15]), "=r"((r)[16]), "=r"((r)[17]), \
          "=r"((r)[18]), "=r"((r)[19]), "=r"((r)[20]), "=r"((r)[21]), "=r"((r)[22]), "=r"((r)[23]), \
          "=r"((r)[24]), "=r"((r)[25]), "=r"((r)[26]), "=r"((r)[27]), "=r"((r)[28]), "=r"((r)[29]), \
          "=r"((r)[30]), "=r"((r)[31]) : "r"(ta))

#if TC_OK
__device__ __forceinline__ void mma_bf16_ss(uint32_t d, uint64_t a, uint64_t b,
                                            uint32_t idesc, bool en) {
    uint32_t e = en ? 1u : 0u;
    asm volatile(
        "{\n\t.reg .pred p;\n\tsetp.ne.u32 p, %5, 0;\n\t"
        "tcgen05.mma.cta_group::1.kind::f16 [%0], %1, %2, %3, {%4, %4, %4, %4}, p;\n\t}"
        :: "r"(d), "l"(a), "l"(b), "r"(idesc), "r"(0u), "r"(e) : "memory");
}
#endif

// SW128 smem descriptor: layout=2, version=1, SBO=64, LBO=1
__device__ __forceinline__ uint64_t make_desc(uint32_t addr) {
    const uint64_t base = (2ull << 61) | (1ull << 46) | (64ull << 32) | (1ull << 16);
    return base | ((uint64_t)(addr >> 4) & 0x3FFF);
}

// idesc: F32 accum, BF16 a/b, N=128, M=128  (same construction as verified 0x8080490 N=32 case)
#define MMA_IDESC ((1u << 4) | (1u << 7) | (1u << 10) | ((128u / 8) << 17) | ((128u / 16) << 24))

__device__ __forceinline__ int edge_val(const void* edges, long long idx) {
    if (g_i64) return (int)((const long long*)edges)[idx];
    return ((const int*)edges)[idx];
}
__device__ __forceinline__ void bf16_split(float x, __nv_bfloat16& h, __nv_bfloat16& l) {
    h = __float2bfloat16(x);
    l = __float2bfloat16(x - __bfloat162float(h));
}
// f32x2 helpers for fallback
__device__ __forceinline__ unsigned long long pack2(float x, float y) {
    unsigned long long d;
    asm("mov.b64 %0, {%1, %2};" : "=l"(d) : "f"(x), "f"(y));
    return d;
}
__device__ __forceinline__ unsigned long long fma2(unsigned long long a,
                                                   unsigned long long b,
                                                   unsigned long long c) {
    unsigned long long d;
    asm("fma.rn.f32x2 %0, %1, %2, %3;" : "=l"(d) : "l"(a), "l"(b), "l"(c));
    return d;
}

// ---------------- CSR construction ----------------
__global__ void detect_kernel(const void* edges) {
    const long long* p = (const long long*)edges;
    int lane = threadIdx.x;
    long long v = p[lane];
    bool ok = (v >= 0 && v < NN);
    unsigned m = __ballot_sync(0xffffffff, ok);
    if (lane == 0) g_i64 = (m == 0xffffffffu) ? 1 : 0;
}
__global__ void zero_counts_kernel() {
    int i = blockIdx.x * blockDim.x + threadIdx.x;
    if (i < NN) g_counts[i] = 0;
}
__global__ void count_kernel(const void* edges) {
    int e = blockIdx.x * blockDim.x + threadIdx.x;
    if (e < EE) atomicAdd(&g_counts[edge_val(edges, 2LL * e + 1)], 1);
}
__global__ void scan_block_kernel() {
    __shared__ int s[1024];
    int t = threadIdx.x;
    int i = blockIdx.x * 1024 + t;
    int v = (i < NN) ? g_counts[i] : 0;
    s[t] = v;
    __syncthreads();
#pragma unroll
    for (int d = 1; d < 1024; d <<= 1) {
        int x = (t >= d) ? s[t - d] : 0;
        __syncthreads();
        s[t] += x;
        __syncthreads();
    }
    if (i < NN) g_off[i] = s[t] - v;
    if (t == 1023) g_bsums[blockIdx.x] = s[1023];
}
__global__ void scan_tops_kernel() {
    __shared__ int s[128];
    int t = threadIdx.x;
    int v = (t < SCAN_BLOCKS) ? g_bsums[t] : 0;
    s[t] = v;
    __syncthreads();
#pragma unroll
    for (int d = 1; d < 128; d <<= 1) {
        int x = (t >= d) ? s[t - d] : 0;
        __syncthreads();
        s[t] += x;
        __syncthreads();
    }
    if (t < SCAN_BLOCKS) g_bsum_ex[t] = s[t] - v;
}
__global__ void scan_add_kernel() {
    int i = blockIdx.x * 1024 + threadIdx.x;
    if (i < NN) {
        int o = g_off[i] + g_bsum_ex[blockIdx.x];
        g_off[i] = o;
        g_cursor[i] = o;
    }
    if (i == 0) g_off[NN] = EE;
}
__global__ void scatter_kernel(const void* edges) {
    int e = blockIdx.x * blockDim.x + threadIdx.x;
    if (e < EE) {
        int src = edge_val(edges, 2LL * e);
        int dst = edge_val(edges, 2LL * e + 1);
        g_csr[atomicAdd(&g_cursor[dst], 1)] = src;
    }
}

// ---------------- weight transpose+split: hi/lo bf16 [n][k] + fp32 [k][n] ----------------
__global__ void wconv_kernel(const float* __restrict__ Wbs, const float* __restrict__ Wbn) {
    int idx = blockIdx.x * 256 + threadIdx.x;   // 4*256*256 = 262144
    int l = idx >> 16, n = (idx >> 8) & 255, k = idx & 255;
    float v = 0.f;
    if (k < BIN)
        v = (n < 128) ? Wbs[(size_t)l * BIN * HH + k * 128 + n]
                      : Wbn[(size_t)l * BIN * HH + k * 128 + (n - 128)];
    __nv_bfloat16 h, lo;
    bf16_split(v, h, lo);
    g_Whi[idx] = h;
    g_Wlo[idx] = lo;
    g_Wf[(((size_t)l * 256) + k) * 256 + n] = v;   // [l][k][n] for SIMT fallback
}

// ---------------- zero A pad cols [198,256) ----------------
__global__ void zero_pad_kernel() {
    long long idx = (long long)blockIdx.x * blockDim.x + threadIdx.x;  // NN*58
    if (idx >= (long long)NN * 58) return;
    int n = (int)(idx / 58);
    int c = 198 + (int)(idx % 58);
    g_Ahi[(size_t)n * 256 + c] = __float2bfloat16(0.f);
    g_Alo[(size_t)n * 256 + c] = __float2bfloat16(0.f);
}

// ---------------- layer 0 GEMM ----------------
__global__ void l0_gemm_kernel(const float* __restrict__ vert,
                               const float* __restrict__ vpot,
                               const float* __restrict__ W0s,
                               const float* __restrict__ W0n) {
    int n = blockIdx.x;
    int c = threadIdx.x;
    __shared__ float xi[6];
    if (c < 6) xi[c] = (c < 3) ? vert[n * 3 + c] : vpot[n * 3 + (c - 3)];
    __syncthreads();
    const float* B = (c < 128) ? (W0s + c) : (W0n + (c - 128));
    float acc = 0.f;
#pragma unroll
    for (int k = 0; k < 6; k++) acc += xi[k] * B[k * HH];
    g_t[(size_t)n * 256 + c] = acc;
}

// ---------------- combine (body): agg+bias+relu, write bf16 A (feat|z|in6) --------
__global__ void combine_body_kernel(const float* __restrict__ bias,
                                    const float* __restrict__ zi,
                                    const float* __restrict__ vert,
                                    const float* __restrict__ vpot) {
    int gw = (blockIdx.x * blockDim.x + threadIdx.x) >> 5;
    int lane = threadIdx.x & 31;
    if (gw >= NN) return;
    int n = gw;
    int s0 = g_off[n], s1 = g_off[n + 1];
    float4 acc = make_float4(0.f, 0.f, 0.f, 0.f);
    for (int e = s0; e < s1; e++) {
        int s = g_csr[e];
        float4 v = *((const float4*)(g_t + (size_t)s * 256 + 128) + lane);
        acc.x += v.x; acc.y += v.y; acc.z += v.z; acc.w += v.w;
    }
    float inv = 1.0f / (float)max(s1 - s0, 1);
    float4 ts = *((const float4*)(g_t + (size_t)n * 256) + lane);
    float4 b4 = ((const float4*)bias)[lane];
    float o[4];
    o[0] = fmaxf(ts.x + acc.x * inv + b4.x, 0.f);
    o[1] = fmaxf(ts.y + acc.y * inv + b4.y, 0.f);
    o[2] = fmaxf(ts.z + acc.z * inv + b4.z, 0.f);
    o[3] = fmaxf(ts.w + acc.w * inv + b4.w, 0.f);
    __nv_bfloat16 h[4], l[4];
#pragma unroll
    for (int j = 0; j < 4; j++) bf16_split(o[j], h[j], l[j]);
    *(uint2*)(g_Ahi + (size_t)n * 256 + lane * 4) = *(const uint2*)h;
    *(uint2*)(g_Alo + (size_t)n * 256 + lane * 4) = *(const uint2*)l;
    float2 zv = *(const float2*)(zi + (size_t)n * 64 + lane * 2);
    __nv_bfloat16 zh[2], zl[2];
    bf16_split(zv.x, zh[0], zl[0]);
    bf16_split(zv.y, zh[1], zl[1]);
    *(uint32_t*)(g_Ahi + (size_t)n * 256 + 128 + lane * 2) = *(const uint32_t*)zh;
    *(uint32_t*)(g_Alo + (size_t)n * 256 + 128 + lane * 2) = *(const uint32_t*)zl;
    if (lane < 6) {
        float v = (lane < 3) ? vert[n * 3 + lane] : vpot[n * 3 + lane - 3];
        __nv_bfloat16 ih, il;
        bf16_split(v, ih, il);
        g_Ahi[(size_t)n * 256 + 192 + lane] = ih;
        g_Alo[(size_t)n * 256 + 192 + lane] = il;
    }
}

// ---------------- combine (head): agg+bias+relu -> fp32 g_feat ----------------
__global__ void combine_head_kernel(const float* __restrict__ bias) {
    int gw = (blockIdx.x * blockDim.x + threadIdx.x) >> 5;
    int lane = threadIdx.x & 31;
    if (gw >= NN) return;
    int n = gw;
    int s0 = g_off[n], s1 = g_off[n + 1];
    float4 acc = make_float4(0.f, 0.f, 0.f, 0.f);
    for (int e = s0; e < s1; e++) {
        int s = g_csr[e];
        float4 v = *((const float4*)(g_t + (size_t)s * 256 + 128) + lane);
        acc.x += v.x; acc.y += v.y; acc.z += v.z; acc.w += v.w;
    }
    float inv = 1.0f / (float)max(s1 - s0, 1);
    float4 ts = *((const float4*)(g_t + (size_t)n * 256) + lane);
    float4 b4 = ((const float4*)bias)[lane];
    float4 o;
    o.x = fmaxf(ts.x + acc.x * inv + b4.x, 0.f);
    o.y = fmaxf(ts.y + acc.y * inv + b4.y, 0.f);
    o.z = fmaxf(ts.z + acc.z * inv + b4.z, 0.f);
    o.w = fmaxf(ts.w + acc.w * inv + b4.w, 0.f);
    *((float4*)(g_feat + (size_t)n * HH) + lane) = o;
}

// ---------------- body GEMM: tcgen05 when available, SIMT f32x2 otherwise ----------
#define ST_BYTES 98304
#define SMEM_TILES 1024
#define GEMM_SMEM (SMEM_TILES + 2 * ST_BYTES)   // 197632

__global__ void __launch_bounds__(256, 1)
tc_gemm_kernel(int layer) {
#if TC_OK
    // ======================= tcgen05 bf16 split path =======================
    extern __shared__ char smem[];
    uint32_t sb = smem_to_u32(smem);
    int tid = threadIdx.x;
    int wid = tid >> 5;
    int row0 = blockIdx.x * 128;

    if (wid == 0) {
        TCGEN05_ALLOC(sb, 256);
        TCGEN05_RELINQ();
    }
    if (tid == 0) {
        MBARRIER_INIT(sb + 8, 1);
        MBARRIER_INIT(sb + 16, 1);
    }
    __syncthreads();
    uint32_t tmem;
    asm volatile("ld.shared.b32 %0, [%1];" : "=r"(tmem) : "r"(sb));

    const __nv_bfloat16* Wh = g_Whi + (size_t)layer * 65536;
    const __nv_bfloat16* Wl = g_Wlo + (size_t)layer * 65536;

    auto load_stage = [&](int kc, int st) {
        char* base = smem + SMEM_TILES + st * ST_BYTES;
        int c0 = kc * 64;
#pragma unroll
        for (int i = 0; i < 4; i++) {           // A: 128 rows x 128B (hi & lo)
            int u = tid + i * 256;
            int m = u >> 3, j = u & 7;
            int n = row0 + m;
            uint4 vh = make_uint4(0u, 0u, 0u, 0u), vl = vh;
            if (n < NN) {
                vh = *(const uint4*)(g_Ahi + (size_t)n * 256 + c0 + j * 8);
                vl = *(const uint4*)(g_Alo + (size_t)n * 256 + c0 + j * 8);
            }
            uint32_t off = SMEM_SWIZZLE_128B((uint32_t)(m * 128 + j * 16));
            *(uint4*)(base + off) = vh;
            *(uint4*)(base + 16384 + off) = vl;
        }
#pragma unroll
        for (int i = 0; i < 8; i++) {           // B: 256 rows x 128B (hi & lo)
            int u = tid + i * 256;
            int r = u >> 3, j = u & 7;
            uint4 vh = *(const uint4*)(Wh + (size_t)r * 256 + c0 + j * 8);
            uint4 vl = *(const uint4*)(Wl + (size_t)r * 256 + c0 + j * 8);
            uint32_t off = SMEM_SWIZZLE_128B((uint32_t)(r * 128 + j * 16));
            *(uint4*)(base + 32768 + off) = vh;
            *(uint4*)(base + 65536 + off) = vl;
        }
    };

    load_stage(0, 0);
    FENCE_ASYNC();
    __syncthreads();

    for (int c = 0; c < 4; c++) {
        int st = c & 1;
        if (wid == 0 && elect_one_pred()) {
            uint32_t tb = sb + SMEM_TILES + st * ST_BYTES;
            uint64_t ah = make_desc(tb);
            uint64_t al = make_desc(tb + 16384);
            uint64_t bh = make_desc(tb + 32768);
            uint64_t bl = make_desc(tb + 65536);
#pragma unroll
            for (int k = 0; k < 4; k++) {
                bool en = !(c == 0 && k == 0);
                // N-half 0 (B rows 0-127) -> D cols 0-127
                mma_bf16_ss(tmem,       ah + k * 2, bh + k * 2,        MMA_IDESC, en);
                mma_bf16_ss(tmem,       ah + k * 2, bl + k * 2,        MMA_IDESC, true);
                mma_bf16_ss(tmem,       al + k * 2, bh + k * 2,        MMA_IDESC, true);
                // N-half 1 (B rows 128-255, +1024 desc units) -> D cols 128-255
                mma_bf16_ss(tmem + 128, ah + k * 2, bh + 1024 + k * 2, MMA_IDESC, en);
                mma_bf16_ss(tmem + 128, ah + k * 2, bl + 1024 + k * 2, MMA_IDESC, true);
                mma_bf16_ss(tmem + 128, al + k * 2, bh + 1024 + k * 2, MMA_IDESC, true);
            }
            TCGEN05_COMMIT(sb + 8 + 8 * st);
        }
        if (c < 3) {
            if (c >= 1) MBARRIER_WAIT_PARITY(sb + 8 + 8 * ((c + 1) & 1), 0);
            load_stage(c + 1, st ^ 1);
            FENCE_ASYNC();
        }
        __syncthreads();
    }

    MBARRIER_WAIT_PARITY(sb + 8, 1);
    MBARRIER_WAIT_PARITY(sb + 16, 1);
    TCGEN05_FENCE_AFTER();

    if (wid < 4) {
        int lane = tid & 31;
        int n = row0 + wid * 32 + lane;
#pragma unroll
        for (int cb = 0; cb < 256; cb += 32) {
            uint32_t r[32];
            TCGEN05_LD_X32(r, tmem + cb);
            TCGEN05_WAIT_LD();
            if (n < NN) {
                float* dst = g_t + (size_t)n * 256 + cb;
#pragma unroll
                for (int j = 0; j < 32; j += 4)
                    *(uint4*)(dst + j) = make_uint4(r[j], r[j + 1], r[j + 2], r[j + 3]);
            }
        }
        TCGEN05_FENCE_BEFORE();
    }
    __syncthreads();
    if (wid == 0) TCGEN05_DEALLOC(tmem, 256);
#else
    // ======================= SIMT f32x2 fallback path =======================
    extern __shared__ char smem[];
    float (*As)[16][132] = reinterpret_cast<float(*)[16][132]>(smem);
    float (*Bs)[16][128] = reinterpret_cast<float(*)[16][128]>(smem + 2 * 16 * 132 * 4);

    const int tid = threadIdx.x;
    const int tx = tid & 15;
    const int ty = tid >> 4;
    const int row0 = blockIdx.x * 128;
    const float* Wf = g_Wf + (size_t)layer * 65536;

    for (int half = 0; half < 2; half++) {
        const int col0 = half * 128;
        unsigned long long acc[8][4];
#pragma unroll
        for (int i = 0; i < 8; i++)
#pragma unroll
            for (int j = 0; j < 4; j++) acc[i][j] = 0ull;

        float ra[8], rb[8];
        auto loadA = [&](int kt, float* r) {
            int kbase = kt * 16;
#pragma unroll
            for (int j = 0; j < 8; j++) {
                int l = tid + j * 256;
                int m = l >> 4, kk = l & 15;
                int n = row0 + m;
                int k = kbase + kk;
                float v = 0.f;
                if (n < NN)
                    v = __bfloat162float(g_Ahi[(size_t)n * 256 + k]) +
                        __bfloat162float(g_Alo[(size_t)n * 256 + k]);
                r[j] = v;
            }
        };
        auto loadB = [&](int kt, float* r) {
            int kbase = kt * 16;
#pragma unroll
            for (int j = 0; j < 8; j++) {
                int l = tid + j * 256;
                int c = l & 127;
                int k = kbase + (l >> 7);
                r[j] = Wf[(size_t)k * 256 + col0 + c];
            }
        };
        auto storeA = [&](int st, const float* r) {
#pragma unroll
            for (int j = 0; j < 8; j++) {
                int l = tid + j * 256;
                As[st][l & 15][l >> 4] = r[j];
            }
        };
        auto storeB = [&](int st, const float* r) {
#pragma unroll
            for (int j = 0; j < 8; j++) {
                int l = tid + j * 256;
                Bs[st][l >> 7][l & 127] = r[j];
            }
        };

        loadA(0, ra); loadB(0, rb);
        storeA(0, ra); storeB(0, rb);
        __syncthreads();

        for (int kt = 0; kt < 13; kt++) {     // 13*16 = 208 >= 198 (cols 198-207 zero)
            int cur = kt & 1;
            if (kt < 12) { loadA(kt + 1, ra); loadB(kt + 1, rb); }
#pragma unroll
            for (int kk = 0; kk < 16; kk++) {
                float4 a0 = *(const float4*)&As[cur][kk][ty * 8];
                float4 a1 = *(const float4*)&As[cur][kk][ty * 8 + 4];
                ulonglong2 b0 = *(const ulonglong2*)&Bs[cur][kk][tx * 4];
                ulonglong2 b1 = *(const ulonglong2*)&Bs[cur][kk][64 + tx * 4];
                unsigned long long ad[8];
                ad[0] = pack2(a0.x, a0.x); ad[1] = pack2(a0.y, a0.y);
                ad[2] = pack2(a0.z, a0.z); ad[3] = pack2(a0.w, a0.w);
                ad[4] = pack2(a1.x, a1.x); ad[5] = pack2(a1.y, a1.y);
                ad[6] = pack2(a1.z, a1.z); ad[7] = pack2(a1.w, a1.w);
#pragma unroll
                for (int i = 0; i < 8; i++) {
                    acc[i][0] = fma2(ad[i], b0.x, acc[i][0]);
                    acc[i][1] = fma2(ad[i], b0.y, acc[i][1]);
                    acc[i][2] = fma2(ad[i], b1.x, acc[i][2]);
                    acc[i][3] = fma2(ad[i], b1.y, acc[i][3]);
                }
            }
            if (kt < 12) { storeA(cur ^ 1, ra); storeB(cur ^ 1, rb); }
            __syncthreads();
        }

#pragma unroll
        for (int i = 0; i < 8; i++) {
            int n = row0 + ty * 8 + i;
            if (n < NN) {
                float* base = g_t + (size_t)n * 256 + col0;
                ulonglong2 v0; v0.x = acc[i][0]; v0.y = acc[i][1];
                ulonglong2 v1; v1.x = acc[i][2]; v1.y = acc[i][3];
                *(ulonglong2*)(base + tx * 4) = v0;
                *(ulonglong2*)(base + 64 + tx * 4) = v1;
            }
        }
        __syncthreads();
    }
#endif
}

// ---------------- head GEMM + combine ----------------
__global__ void final_gemm_kernel(const float* __restrict__ Wls,
                                  const float* __restrict__ Wln) {
    __shared__ float B[128][6];
    int tid = threadIdx.x;
    for (int i = tid; i < 128 * 6; i += 256) {
        int k = i / 6, c = i % 6;
        B[k][c] = (c < 3) ? Wls[k * 3 + c] : Wln[k * 3 + (c - 3)];
    }
    __syncthreads();
    int gw = (blockIdx.x * 256 + tid) >> 5;
    int lane = tid & 31;
    if (gw >= NN) return;
    int n = gw;
    float p0 = 0.f, p1 = 0.f, p2 = 0.f, p3 = 0.f, p4 = 0.f, p5 = 0.f;
    for (int k = lane; k < 128; k += 32) {
        float f = g_feat[(size_t)n * 128 + k];
        p0 += f * B[k][0]; p1 += f * B[k][1]; p2 += f * B[k][2];
        p3 += f * B[k][3]; p4 += f * B[k][4]; p5 += f * B[k][5];
    }
#pragma unroll
    for (int o = 16; o > 0; o >>= 1) {
        p0 += __shfl_xor_sync(0xffffffff, p0, o);
        p1 += __shfl_xor_sync(0xffffffff, p1, o);
        p2 += __shfl_xor_sync(0xffffffff, p2, o);
        p3 += __shfl_xor_sync(0xffffffff, p3, o);
        p4 += __shfl_xor_sync(0xffffffff, p4, o);
        p5 += __shfl_xor_sync(0xffffffff, p5, o);
    }
    if (lane == 0) {
        g_t[(size_t)n * 6 + 0] = p0;
        g_t[(size_t)n * 6 + 1] = p1;
        g_t[(size_t)n * 6 + 2] = p2;
        g_t[(size_t)n * 6 + 3] = p3;
        g_t[(size_t)n * 6 + 4] = p4;
        g_t[(size_t)n * 6 + 5] = p5;
    }
}

__global__ void final_combine_kernel(const float* __restrict__ bl,
                                     float* __restrict__ out) {
    int n = blockIdx.x * blockDim.x + threadIdx.x;
    if (n >= NN) return;
    int s0 = g_off[n], s1 = g_off[n + 1];
    float a0 = 0.f, a1 = 0.f, a2 = 0.f;
    for (int e = s0; e < s1; e++) {
        int s = g_csr[e];
        a0 += g_t[(size_t)s * 6 + 3];
        a1 += g_t[(size_t)s * 6 + 4];
        a2 += g_t[(size_t)s * 6 + 5];
    }
    float inv = 1.0f / (float)max(s1 - s0, 1);
    out[n * 3 + 0] = g_t[(size_t)n * 6 + 0] + a0 * inv + bl[0];
    out[n * 3 + 1] = g_t[(size_t)n * 6 + 1] + a1 * inv + bl[1];
    out[n * 3 + 2] = g_t[(size_t)n * 6 + 2] + a2 * inv + bl[2];
}

// ---------------- launch ----------------
extern "C" void kernel_launch(void* const* d_in, const int* in_sizes, int n_in,
                              void* d_out, int out_size) {
    const float* vert = (const float*)d_in[0];
    const void*  edges = d_in[1];
    const float* vpot = (const float*)d_in[2];
    const float* z    = (const float*)d_in[3];
    const float* W0s  = (const float*)d_in[4];
    const float* W0n  = (const float*)d_in[5];
    const float* b0   = (const float*)d_in[6];
    const float* Wbs  = (const float*)d_in[7];
    const float* Wbn  = (const float*)d_in[8];
    const float* bb   = (const float*)d_in[9];
    const float* Wls  = (const float*)d_in[10];
    const float* Wln  = (const float*)d_in[11];
    const float* bl   = (const float*)d_in[12];
    float* out = (float*)d_out;

    cudaFuncSetAttribute(tc_gemm_kernel, cudaFuncAttributeMaxDynamicSharedMemorySize, GEMM_SMEM);

    // CSR build
    detect_kernel<<<1, 32>>>(edges);
    zero_counts_kernel<<<(NN + 1023) / 1024, 1024>>>();
    count_kernel<<<(EE + 255) / 256, 256>>>(edges);
    scan_block_kernel<<<SCAN_BLOCKS, 1024>>>();
    scan_tops_kernel<<<1, 128>>>();
    scan_add_kernel<<<SCAN_BLOCKS, 1024>>>();
    scatter_kernel<<<(EE + 255) / 256, 256>>>(edges);

    // weight split + A pad zero
    wconv_kernel<<<1024, 256>>>(Wbs, Wbn);
    zero_pad_kernel<<<(int)(((long long)NN * 58 + 255) / 256), 256>>>();

    // layer 0
    l0_gemm_kernel<<<NN, 256>>>(vert, vpot, W0s, W0n);
    combine_body_kernel<<<(NN * 32 + 255) / 256, 256>>>(b0, z, vert, vpot);

    // 4 body layers
    for (int i = 0; i < 4; i++) {
        tc_gemm_kernel<<<MTILES, 256, GEMM_SMEM>>>(i);
        if (i < 3)
            combine_body_kernel<<<(NN * 32 + 255) / 256, 256>>>(
                bb + i * HH, z + (size_t)(i + 1) * NN * ZZ, vert, vpot);
        else
            combine_head_kernel<<<(NN * 32 + 255) / 256, 256>>>(bb + 3 * HH);
    }

    // head
    final_gemm_kernel<<<(NN * 32 + 255) / 256, 256>>>(Wls, Wln);
    final_combine_kernel<<<(NN + 255) / 256, 256>>>(bl, out);
}

// round 5
// speedup vs baseline: 3.1484x; 1.1357x over previous
#include <cuda_runtime.h>
#include <cuda_bf16.h>
#include <cstdint>

#define NN 100000
#define EE 600000
#define HH 128
#define ZZ 64
#define BIN 198
#define SCAN_BLOCKS ((NN + 1023) / 1024)   // 98
#define MTILES ((NN + 127) / 128)          // 782

// ---------------- device scratch (no allocations allowed) ----------------
__device__ int   g_i64;
__device__ int   g_counts[NN];
__device__ int   g_off[NN + 1];
__device__ int   g_cursor[NN];
__device__ int   g_csr[EE];
__device__ int   g_bsums[SCAN_BLOCKS];
__device__ int   g_bsum_ex[SCAN_BLOCKS];
__device__ float g_feat[(size_t)NN * HH];          // fp32 feat (head input only)
__device__ float g_t[(size_t)NN * 256];            // GEMM out: cols 0-127 s-half, 128-255 n-half
__device__ __nv_bfloat16 g_Ahi[(size_t)NN * 256];  // concat A, hi part (cols 0..207 used)
__device__ __nv_bfloat16 g_Alo[(size_t)NN * 256];  // lo part
__device__ __nv_bfloat16 g_Whi[4 * 256 * 256];     // [layer][n(256)][k(256)] transposed weights
__device__ __nv_bfloat16 g_Wlo[4 * 256 * 256];
__device__ float g_Wf[4 * 256 * 256];              // [layer][k(256)][n(256)] fp32 (fallback path)

// ---------------- arch feature gate ----------------
#if defined(__CUDA_ARCH_FEAT_SM103_ALL) || defined(__CUDA_ARCH_FEAT_SM100_ALL) || \
    defined(__CUDA_ARCH_FEAT_SM101_ALL) || defined(__CUDA_ARCH_FEAT_SM110_ALL)
#define TC_OK 1
#else
#define TC_OK 0
#endif

// ---------------- PTX helpers ----------------
__device__ __forceinline__ uint32_t elect_one_pred() {
    uint32_t pred;
    asm volatile("{\n\t.reg .pred p;\n\telect.sync _|p, 0xFFFFFFFF;\n\tselp.b32 %0, 1, 0, p;\n\t}"
                 : "=r"(pred));
    return pred;
}
__device__ __forceinline__ uint32_t smem_to_u32(const void* p) {
    uint32_t a;
    asm("{ .reg .u64 t; cvta.to.shared.u64 t, %1; cvt.u32.u64 %0, t; }" : "=r"(a) : "l"(p));
    return a;
}
#define SMEM_SWIZZLE_128B(x) ((x) ^ (((x) >> 3) & 0x70))

#define TCGEN05_ALLOC(sa, n) \
    asm volatile("tcgen05.alloc.cta_group::1.sync.aligned.shared::cta.b32 [%0], %1;" \
                 :: "r"((uint32_t)(sa)), "r"((uint32_t)(n)) : "memory")
#define TCGEN05_DEALLOC(t, n) \
    asm volatile("tcgen05.dealloc.cta_group::1.sync.aligned.b32 %0, %1;" :: "r"(t), "r"(n))
#define TCGEN05_RELINQ() \
    asm volatile("tcgen05.relinquish_alloc_permit.cta_group::1.sync.aligned;")
#define TCGEN05_COMMIT(mb) \
    asm volatile("tcgen05.commit.cta_group::1.mbarrier::arrive::one.shared::cluster.b64 [%0];" \
                 :: "r"((uint32_t)(mb)) : "memory")
#define TCGEN05_FENCE_AFTER() asm volatile("tcgen05.fence::after_thread_sync;" ::: "memory")
#define TCGEN05_FENCE_BEFORE() asm volatile("tcgen05.fence::before_thread_sync;" ::: "memory")
#define TCGEN05_WAIT_LD() asm volatile("tcgen05.wait::ld.sync.aligned;" ::: "memory")
#define FENCE_ASYNC() asm volatile("fence.proxy.async.shared::cta;" ::: "memory")
#define MBARRIER_INIT(mb, c) \
    asm volatile("mbarrier.init.shared.b64 [%0], %1;" :: "r"((uint32_t)(mb)), "r"((uint32_t)(c)) : "memory")

#define MBARRIER_WAIT_PARITY(mb, ph) do { \
    uint32_t _m = (uint32_t)(mb), _p = (uint32_t)(ph), _d; \
    asm volatile("{\n\t.reg .pred p;\n\t" \
        "mbarrier.try_wait.parity.acquire.cta.shared::cta.b64 p, [%1], %2;\n\t" \
        "selp.b32 %0, 1, 0, p;\n\t}" : "=r"(_d) : "r"(_m), "r"(_p) : "memory"); \
    if (!_d) { \
        asm volatile("{\n\t.reg .pred P1;\n\t" \
            "WL_%=:\n\t" \
            "mbarrier.try_wait.parity.acquire.cta.shared::cta.b64 P1, [%0], %1, 0x989680;\n\t" \
            "@P1 bra.uni WD_%=;\n\tbra.uni WL_%=;\n\tWD_%=:\n\t}" \
            :: "r"(_m), "r"(_p) : "memory"); \
    } \
} while (0)

#define TCGEN05_LD_X32(r, ta) \
    asm volatile("tcgen05.ld.sync.aligned.32x32b.x32.b32 " \
        "{%0, %1, %2, %3, %4, %5, %6, %7, %8, %9, %10, %11, %12, %13, %14, %15, " \
        "%16, %17, %18, %19, %20, %21, %22, %23, %24, %25, %26, %27, %28, %29, %30, %31}, [%32];" \
        : "=r"((r)[0]), "=r"((r)[1]), "=r"((r)[2]), "=r"((r)[3]), "=r"((r)[4]), "=r"((r)[5]), \
          "=r"((r)[6]), "=r"((r)[7]), "=r"((r)[8]), "=r"((r)[9]), "=r"((r)[10]), "=r"((r)[11]), \
          "=r"((r)[12]), "=r"((r)[13]), "=r"((r)[14]), "=r"((r)[15]), "=r"((r)[16]), "=r"((r)[17]), \
          "=r"((r)[18]), "=r"((r)[19]), "=r"((r)[20]), "=r"((r)[21]), "=r"((r)[22]), "=r"((r)[23]), \
          "=r"((r)[24]), "=r"((r)[25]), "=r"((r)[26]), "=r"((r)[27]), "=r"((r)[28]), "=r"((r)[29]), \
          "=r"((r)[30]), "=r"((r)[31]) : "r"(ta))

#if TC_OK
__device__ __forceinline__ void mma_bf16_ss(uint32_t d, uint64_t a, uint64_t b,
                                            uint32_t idesc, bool en) {
    uint32_t e = en ? 1u : 0u;
    asm volatile(
        "{\n\t.reg .pred p;\n\tsetp.ne.u32 p, %5, 0;\n\t"
        "tcgen05.mma.cta_group::1.kind::f16 [%0], %1, %2, %3, {%4, %4, %4, %4}, p;\n\t}"
        :: "r"(d), "l"(a), "l"(b), "r"(idesc), "r"(0u), "r"(e) : "memory");
}
#endif

// SW128 smem descriptor: layout=2, version=1, SBO=64, LBO=1
__device__ __forceinline__ uint64_t make_desc(uint32_t addr) {
    const uint64_t base = (2ull << 61) | (1ull << 46) | (64ull << 32) | (1ull << 16);
    return base | ((uint64_t)(addr >> 4) & 0x3FFF);
}

// idesc: F32 accum, BF16 a/b, N=128, M=128
#define MMA_IDESC ((1u << 4) | (1u << 7) | (1u << 10) | ((128u / 8) << 17) | ((128u / 16) << 24))

__device__ __forceinline__ int2 edge_pair(const void* edges, int e) {
    if (g_i64) {
        longlong2 v = ((const longlong2*)edges)[e];
        return make_int2((int)v.x, (int)v.y);
    }
    return ((const int2*)edges)[e];
}
__device__ __forceinline__ void bf16_split(float x, __nv_bfloat16& h, __nv_bfloat16& l) {
    h = __float2bfloat16(x);
    l = __float2bfloat16(x - __bfloat162float(h));
}
__device__ __forceinline__ unsigned long long pack2(float x, float y) {
    unsigned long long d;
    asm("mov.b64 %0, {%1, %2};" : "=l"(d) : "f"(x), "f"(y));
    return d;
}
__device__ __forceinline__ unsigned long long fma2(unsigned long long a,
                                                   unsigned long long b,
                                                   unsigned long long c) {
    unsigned long long d;
    asm("fma.rn.f32x2 %0, %1, %2, %3;" : "=l"(d) : "l"(a), "l"(b), "l"(c));
    return d;
}

// ---------------- CSR construction ----------------
__global__ void detect_kernel(const void* edges) {
    const long long* p = (const long long*)edges;
    int lane = threadIdx.x;
    long long v = p[lane];
    bool ok = (v >= 0 && v < NN);
    unsigned m = __ballot_sync(0xffffffff, ok);
    if (lane == 0) g_i64 = (m == 0xffffffffu) ? 1 : 0;
}
__global__ void zero_counts_kernel() {
    int i = blockIdx.x * blockDim.x + threadIdx.x;
    if (i < NN) g_counts[i] = 0;
}
__global__ void count_kernel(const void* edges) {
    int e = blockIdx.x * blockDim.x + threadIdx.x;
    if (e < EE) atomicAdd(&g_counts[edge_pair(edges, e).y], 1);
}
__global__ void scan_block_kernel() {
    __shared__ int s[1024];
    int t = threadIdx.x;
    int i = blockIdx.x * 1024 + t;
    int v = (i < NN) ? g_counts[i] : 0;
    s[t] = v;
    __syncthreads();
#pragma unroll
    for (int d = 1; d < 1024; d <<= 1) {
        int x = (t >= d) ? s[t - d] : 0;
        __syncthreads();
        s[t] += x;
        __syncthreads();
    }
    if (i < NN) g_off[i] = s[t] - v;
    if (t == 1023) g_bsums[blockIdx.x] = s[1023];
}
__global__ void scan_tops_kernel() {
    __shared__ int s[128];
    int t = threadIdx.x;
    int v = (t < SCAN_BLOCKS) ? g_bsums[t] : 0;
    s[t] = v;
    __syncthreads();
#pragma unroll
    for (int d = 1; d < 128; d <<= 1) {
        int x = (t >= d) ? s[t - d] : 0;
        __syncthreads();
        s[t] += x;
        __syncthreads();
    }
    if (t < SCAN_BLOCKS) g_bsum_ex[t] = s[t] - v;
}
__global__ void scan_add_kernel() {
    int i = blockIdx.x * 1024 + threadIdx.x;
    if (i < NN) {
        int o = g_off[i] + g_bsum_ex[blockIdx.x];
        g_off[i] = o;
        g_cursor[i] = o;
    }
    if (i == 0) g_off[NN] = EE;
}
__global__ void scatter_kernel(const void* edges) {
    int e = blockIdx.x * blockDim.x + threadIdx.x;
    if (e < EE) {
        int2 p = edge_pair(edges, e);
        g_csr[atomicAdd(&g_cursor[p.y], 1)] = p.x;
    }
}

// ---------------- weight transpose+split ----------------
__global__ void wconv_kernel(const float* __restrict__ Wbs, const float* __restrict__ Wbn) {
    int idx = blockIdx.x * 256 + threadIdx.x;   // 4*256*256
    int l = idx >> 16, n = (idx >> 8) & 255, k = idx & 255;
    float v = 0.f;
    if (k < BIN)
        v = (n < 128) ? Wbs[(size_t)l * BIN * HH + k * 128 + n]
                      : Wbn[(size_t)l * BIN * HH + k * 128 + (n - 128)];
    __nv_bfloat16 h, lo;
    bf16_split(v, h, lo);
    g_Whi[idx] = h;
    g_Wlo[idx] = lo;
    g_Wf[(((size_t)l * 256) + k) * 256 + n] = v;
}

// ---------------- zero A pad cols [198,208) ----------------
__global__ void zero_pad_kernel() {
    long long idx = (long long)blockIdx.x * blockDim.x + threadIdx.x;  // NN*10
    if (idx >= (long long)NN * 10) return;
    int n = (int)(idx / 10);
    int c = 198 + (int)(idx % 10);
    g_Ahi[(size_t)n * 256 + c] = __float2bfloat16(0.f);
    g_Alo[(size_t)n * 256 + c] = __float2bfloat16(0.f);
}

// ---------------- layer 0 GEMM: 32 nodes per block ----------------
__global__ void __launch_bounds__(256)
l0_gemm_kernel(const float* __restrict__ vert,
               const float* __restrict__ vpot,
               const float* __restrict__ W0s,
               const float* __restrict__ W0n) {
    __shared__ float xi[32][6];
    int t = threadIdx.x;
    int n0 = blockIdx.x * 32;           // NN = 3125*32 exactly
    if (t < 192) {
        int i = t / 6, k = t % 6;
        int n = n0 + i;
        xi[i][k] = (k < 3) ? vert[n * 3 + k] : vpot[n * 3 + (k - 3)];
    }
    __syncthreads();
    int c = t;
    const float* B = (c < 128) ? (W0s + c) : (W0n + (c - 128));
    float w0 = B[0], w1 = B[HH], w2 = B[2 * HH], w3 = B[3 * HH], w4 = B[4 * HH], w5 = B[5 * HH];
#pragma unroll 4
    for (int i = 0; i < 32; i++) {
        float acc = w0 * xi[i][0] + w1 * xi[i][1] + w2 * xi[i][2] +
                    w3 * xi[i][3] + w4 * xi[i][4] + w5 * xi[i][5];
        g_t[(size_t)(n0 + i) * 256 + c] = acc;
    }
}

// ---------------- combine (body): agg+bias+relu -> bf16 A, gather unroll x4 -------
__global__ void combine_body_kernel(const float* __restrict__ bias,
                                    const float* __restrict__ zi,
                                    const float* __restrict__ vert,
                                    const float* __restrict__ vpot) {
    int gw = (blockIdx.x * blockDim.x + threadIdx.x) >> 5;
    int lane = threadIdx.x & 31;
    if (gw >= NN) return;
    int n = gw;
    int s0 = g_off[n], s1 = g_off[n + 1];
    float4 acc = make_float4(0.f, 0.f, 0.f, 0.f);
    int e = s0;
    for (; e + 4 <= s1; e += 4) {
        int i0 = g_csr[e], i1 = g_csr[e + 1], i2 = g_csr[e + 2], i3 = g_csr[e + 3];
        float4 v0 = *((const float4*)(g_t + (size_t)i0 * 256 + 128) + lane);
        float4 v1 = *((const float4*)(g_t + (size_t)i1 * 256 + 128) + lane);
        float4 v2 = *((const float4*)(g_t + (size_t)i2 * 256 + 128) + lane);
        float4 v3 = *((const float4*)(g_t + (size_t)i3 * 256 + 128) + lane);
        acc.x += (v0.x + v1.x) + (v2.x + v3.x);
        acc.y += (v0.y + v1.y) + (v2.y + v3.y);
        acc.z += (v0.z + v1.z) + (v2.z + v3.z);
        acc.w += (v0.w + v1.w) + (v2.w + v3.w);
    }
    for (; e < s1; e++) {
        int s = g_csr[e];
        float4 v = *((const float4*)(g_t + (size_t)s * 256 + 128) + lane);
        acc.x += v.x; acc.y += v.y; acc.z += v.z; acc.w += v.w;
    }
    float inv = 1.0f / (float)max(s1 - s0, 1);
    float4 ts = *((const float4*)(g_t + (size_t)n * 256) + lane);
    float4 b4 = ((const float4*)bias)[lane];
    float o[4];
    o[0] = fmaxf(ts.x + acc.x * inv + b4.x, 0.f);
    o[1] = fmaxf(ts.y + acc.y * inv + b4.y, 0.f);
    o[2] = fmaxf(ts.z + acc.z * inv + b4.z, 0.f);
    o[3] = fmaxf(ts.w + acc.w * inv + b4.w, 0.f);
    __nv_bfloat16 h[4], l[4];
#pragma unroll
    for (int j = 0; j < 4; j++) bf16_split(o[j], h[j], l[j]);
    *(uint2*)(g_Ahi + (size_t)n * 256 + lane * 4) = *(const uint2*)h;
    *(uint2*)(g_Alo + (size_t)n * 256 + lane * 4) = *(const uint2*)l;
    float2 zv = *(const float2*)(zi + (size_t)n * 64 + lane * 2);
    __nv_bfloat16 zh[2], zl[2];
    bf16_split(zv.x, zh[0], zl[0]);
    bf16_split(zv.y, zh[1], zl[1]);
    *(uint32_t*)(g_Ahi + (size_t)n * 256 + 128 + lane * 2) = *(const uint32_t*)zh;
    *(uint32_t*)(g_Alo + (size_t)n * 256 + 128 + lane * 2) = *(const uint32_t*)zl;
    if (lane < 6) {
        float v = (lane < 3) ? vert[n * 3 + lane] : vpot[n * 3 + lane - 3];
        __nv_bfloat16 ih, il;
        bf16_split(v, ih, il);
        g_Ahi[(size_t)n * 256 + 192 + lane] = ih;
        g_Alo[(size_t)n * 256 + 192 + lane] = il;
    }
}

// ---------------- combine (head): agg+bias+relu -> fp32 g_feat ----------------
__global__ void combine_head_kernel(const float* __restrict__ bias) {
    int gw = (blockIdx.x * blockDim.x + threadIdx.x) >> 5;
    int lane = threadIdx.x & 31;
    if (gw >= NN) return;
    int n = gw;
    int s0 = g_off[n], s1 = g_off[n + 1];
    float4 acc = make_float4(0.f, 0.f, 0.f, 0.f);
    int e = s0;
    for (; e + 4 <= s1; e += 4) {
        int i0 = g_csr[e], i1 = g_csr[e + 1], i2 = g_csr[e + 2], i3 = g_csr[e + 3];
        float4 v0 = *((const float4*)(g_t + (size_t)i0 * 256 + 128) + lane);
        float4 v1 = *((const float4*)(g_t + (size_t)i1 * 256 + 128) + lane);
        float4 v2 = *((const float4*)(g_t + (size_t)i2 * 256 + 128) + lane);
        float4 v3 = *((const float4*)(g_t + (size_t)i3 * 256 + 128) + lane);
        acc.x += (v0.x + v1.x) + (v2.x + v3.x);
        acc.y += (v0.y + v1.y) + (v2.y + v3.y);
        acc.z += (v0.z + v1.z) + (v2.z + v3.z);
        acc.w += (v0.w + v1.w) + (v2.w + v3.w);
    }
    for (; e < s1; e++) {
        int s = g_csr[e];
        float4 v = *((const float4*)(g_t + (size_t)s * 256 + 128) + lane);
        acc.x += v.x; acc.y += v.y; acc.z += v.z; acc.w += v.w;
    }
    float inv = 1.0f / (float)max(s1 - s0, 1);
    float4 ts = *((const float4*)(g_t + (size_t)n * 256) + lane);
    float4 b4 = ((const float4*)bias)[lane];
    float4 o;
    o.x = fmaxf(ts.x + acc.x * inv + b4.x, 0.f);
    o.y = fmaxf(ts.y + acc.y * inv + b4.y, 0.f);
    o.z = fmaxf(ts.z + acc.z * inv + b4.z, 0.f);
    o.w = fmaxf(ts.w + acc.w * inv + b4.w, 0.f);
    *((float4*)(g_feat + (size_t)n * HH) + lane) = o;
}

// ---------------- body GEMM: tcgen05 (K=208 trimmed), SIMT fallback ----------
#define ST_BYTES 98304
#define SMEM_TILES 1024
#define GEMM_SMEM (SMEM_TILES + 2 * ST_BYTES)   // 197632

__global__ void __launch_bounds__(256, 1)
tc_gemm_kernel(int layer) {
#if TC_OK
    extern __shared__ char smem[];
    uint32_t sb = smem_to_u32(smem);
    int tid = threadIdx.x;
    int wid = tid >> 5;
    int row0 = blockIdx.x * 128;

    if (wid == 0) {
        TCGEN05_ALLOC(sb, 256);
        TCGEN05_RELINQ();
    }
    if (tid == 0) {
        MBARRIER_INIT(sb + 8, 1);
        MBARRIER_INIT(sb + 16, 1);
    }
    __syncthreads();
    uint32_t tmem;
    asm volatile("ld.shared.b32 %0, [%1];" : "=r"(tmem) : "r"(sb));

    const __nv_bfloat16* Wh = g_Whi + (size_t)layer * 65536;
    const __nv_bfloat16* Wl = g_Wlo + (size_t)layer * 65536;

    // full chunk: 8 x 16B units per 128B row; partial (chunk 3): 2 units (k 192..207)
    auto load_stage = [&](int kc, int st, bool full) {
        char* base = smem + SMEM_TILES + st * ST_BYTES;
        int c0 = kc * 64;
        if (full) {
#pragma unroll
            for (int i = 0; i < 4; i++) {           // A
                int u = tid + i * 256;
                int m = u >> 3, j = u & 7;
                int n = row0 + m;
                uint4 vh = make_uint4(0u, 0u, 0u, 0u), vl = vh;
                if (n < NN) {
                    vh = *(const uint4*)(g_Ahi + (size_t)n * 256 + c0 + j * 8);
                    vl = *(const uint4*)(g_Alo + (size_t)n * 256 + c0 + j * 8);
                }
                uint32_t off = SMEM_SWIZZLE_128B((uint32_t)(m * 128 + j * 16));
                *(uint4*)(base + off) = vh;
                *(uint4*)(base + 16384 + off) = vl;
            }
#pragma unroll
            for (int i = 0; i < 8; i++) {           // B
                int u = tid + i * 256;
                int r = u >> 3, j = u & 7;
                uint4 vh = *(const uint4*)(Wh + (size_t)r * 256 + c0 + j * 8);
                uint4 vl = *(const uint4*)(Wl + (size_t)r * 256 + c0 + j * 8);
                uint32_t off = SMEM_SWIZZLE_128B((uint32_t)(r * 128 + j * 16));
                *(uint4*)(base + 32768 + off) = vh;
                *(uint4*)(base + 65536 + off) = vl;
            }
        } else {
            // A: 128 rows x 2 units = 256 units
            {
                int m = tid >> 1, j = tid & 1;
                int n = row0 + m;
                uint4 vh = make_uint4(0u, 0u, 0u, 0u), vl = vh;
                if (n < NN) {
                    vh = *(const uint4*)(g_Ahi + (size_t)n * 256 + c0 + j * 8);
                    vl = *(const uint4*)(g_Alo + (size_t)n * 256 + c0 + j * 8);
                }
                uint32_t off = SMEM_SWIZZLE_128B((uint32_t)(m * 128 + j * 16));
                *(uint4*)(base + off) = vh;
                *(uint4*)(base + 16384 + off) = vl;
            }
            // B: 256 rows x 2 units = 512 units
#pragma unroll
            for (int i = 0; i < 2; i++) {
                int u = tid + i * 256;
                int r = u >> 1, j = u & 1;
                uint4 vh = *(const uint4*)(Wh + (size_t)r * 256 + c0 + j * 8);
                uint4 vl = *(const uint4*)(Wl + (size_t)r * 256 + c0 + j * 8);
                uint32_t off = SMEM_SWIZZLE_128B((uint32_t)(r * 128 + j * 16));
                *(uint4*)(base + 32768 + off) = vh;
                *(uint4*)(base + 65536 + off) = vl;
            }
        }
    };

    load_stage(0, 0, true);
    FENCE_ASYNC();
    __syncthreads();

    for (int c = 0; c < 4; c++) {
        int st = c & 1;
        int nk = (c < 3) ? 4 : 1;                 // chunk 3: only k 192..207
        if (wid == 0 && elect_one_pred()) {
            uint32_t tb = sb + SMEM_TILES + st * ST_BYTES;
            uint64_t ah = make_desc(tb);
            uint64_t al = make_desc(tb + 16384);
            uint64_t bh = make_desc(tb + 32768);
            uint64_t bl = make_desc(tb + 65536);
            for (int k = 0; k < nk; k++) {
                bool en = !(c == 0 && k == 0);
                mma_bf16_ss(tmem,       ah + k * 2, bh + k * 2,        MMA_IDESC, en);
                mma_bf16_ss(tmem,       ah + k * 2, bl + k * 2,        MMA_IDESC, true);
                mma_bf16_ss(tmem,       al + k * 2, bh + k * 2,        MMA_IDESC, true);
                mma_bf16_ss(tmem + 128, ah + k * 2, bh + 1024 + k * 2, MMA_IDESC, en);
                mma_bf16_ss(tmem + 128, ah + k * 2, bl + 1024 + k * 2, MMA_IDESC, true);
                mma_bf16_ss(tmem + 128, al + k * 2, bh + 1024 + k * 2, MMA_IDESC, true);
            }
            TCGEN05_COMMIT(sb + 8 + 8 * st);
        }
        if (c < 3) {
            if (c >= 1) MBARRIER_WAIT_PARITY(sb + 8 + 8 * ((c + 1) & 1), 0);
            load_stage(c + 1, st ^ 1, (c + 1) < 3);
            FENCE_ASYNC();
        }
        __syncthreads();
    }

    MBARRIER_WAIT_PARITY(sb + 8, 1);
    MBARRIER_WAIT_PARITY(sb + 16, 1);
    TCGEN05_FENCE_AFTER();

    if (wid < 4) {
        int lane = tid & 31;
        int n = row0 + wid * 32 + lane;
#pragma unroll
        for (int cb = 0; cb < 256; cb += 32) {
            uint32_t r[32];
            TCGEN05_LD_X32(r, tmem + cb);
            TCGEN05_WAIT_LD();
            if (n < NN) {
                float* dst = g_t + (size_t)n * 256 + cb;
#pragma unroll
                for (int j = 0; j < 32; j += 4)
                    *(uint4*)(dst + j) = make_uint4(r[j], r[j + 1], r[j + 2], r[j + 3]);
            }
        }
        TCGEN05_FENCE_BEFORE();
    }
    __syncthreads();
    if (wid == 0) TCGEN05_DEALLOC(tmem, 256);
#else
    // ======================= SIMT f32x2 fallback path =======================
    extern __shared__ char smem[];
    float (*As)[16][132] = reinterpret_cast<float(*)[16][132]>(smem);
    float (*Bs)[16][128] = reinterpret_cast<float(*)[16][128]>(smem + 2 * 16 * 132 * 4);

    const int tid = threadIdx.x;
    const int tx = tid & 15;
    const int ty = tid >> 4;
    const int row0 = blockIdx.x * 128;
    const float* Wf = g_Wf + (size_t)layer * 65536;

    for (int half = 0; half < 2; half++) {
        const int col0 = half * 128;
        unsigned long long acc[8][4];
#pragma unroll
        for (int i = 0; i < 8; i++)
#pragma unroll
            for (int j = 0; j < 4; j++) acc[i][j] = 0ull;

        float ra[8], rb[8];
        auto loadA = [&](int kt, float* r) {
            int kbase = kt * 16;
#pragma unroll
            for (int j = 0; j < 8; j++) {
                int l = tid + j * 256;
                int m = l >> 4, kk = l & 15;
                int n = row0 + m;
                int k = kbase + kk;
                float v = 0.f;
                if (n < NN)
                    v = __bfloat162float(g_Ahi[(size_t)n * 256 + k]) +
                        __bfloat162float(g_Alo[(size_t)n * 256 + k]);
                r[j] = v;
            }
        };
        auto loadB = [&](int kt, float* r) {
            int kbase = kt * 16;
#pragma unroll
            for (int j = 0; j < 8; j++) {
                int l = tid + j * 256;
                int c = l & 127;
                int k = kbase + (l >> 7);
                r[j] = Wf[(size_t)k * 256 + col0 + c];
            }
        };
        auto storeA = [&](int st, const float* r) {
#pragma unroll
            for (int j = 0; j < 8; j++) {
                int l = tid + j * 256;
                As[st][l & 15][l >> 4] = r[j];
            }
        };
        auto storeB = [&](int st, const float* r) {
#pragma unroll
            for (int j = 0; j < 8; j++) {
                int l = tid + j * 256;
                Bs[st][l >> 7][l & 127] = r[j];
            }
        };

        loadA(0, ra); loadB(0, rb);
        storeA(0, ra); storeB(0, rb);
        __syncthreads();

        for (int kt = 0; kt < 13; kt++) {
            int cur = kt & 1;
            if (kt < 12) { loadA(kt + 1, ra); loadB(kt + 1, rb); }
#pragma unroll
            for (int kk = 0; kk < 16; kk++) {
                float4 a0 = *(const float4*)&As[cur][kk][ty * 8];
                float4 a1 = *(const float4*)&As[cur][kk][ty * 8 + 4];
                ulonglong2 b0 = *(const ulonglong2*)&Bs[cur][kk][tx * 4];
                ulonglong2 b1 = *(const ulonglong2*)&Bs[cur][kk][64 + tx * 4];
                unsigned long long ad[8];
                ad[0] = pack2(a0.x, a0.x); ad[1] = pack2(a0.y, a0.y);
                ad[2] = pack2(a0.z, a0.z); ad[3] = pack2(a0.w, a0.w);
                ad[4] = pack2(a1.x, a1.x); ad[5] = pack2(a1.y, a1.y);
                ad[6] = pack2(a1.z, a1.z); ad[7] = pack2(a1.w, a1.w);
#pragma unroll
                for (int i = 0; i < 8; i++) {
                    acc[i][0] = fma2(ad[i], b0.x, acc[i][0]);
                    acc[i][1] = fma2(ad[i], b0.y, acc[i][1]);
                    acc[i][2] = fma2(ad[i], b1.x, acc[i][2]);
                    acc[i][3] = fma2(ad[i], b1.y, acc[i][3]);
                }
            }
            if (kt < 12) { storeA(cur ^ 1, ra); storeB(cur ^ 1, rb); }
            __syncthreads();
        }

#pragma unroll
        for (int i = 0; i < 8; i++) {
            int n = row0 + ty * 8 + i;
            if (n < NN) {
                float* base = g_t + (size_t)n * 256 + col0;
                ulonglong2 v0; v0.x = acc[i][0]; v0.y = acc[i][1];
                ulonglong2 v1; v1.x = acc[i][2]; v1.y = acc[i][3];
                *(ulonglong2*)(base + tx * 4) = v0;
                *(ulonglong2*)(base + 64 + tx * 4) = v1;
            }
        }
        __syncthreads();
    }
#endif
}

// ---------------- head GEMM + combine ----------------
__global__ void final_gemm_kernel(const float* __restrict__ Wls,
                                  const float* __restrict__ Wln) {
    __shared__ float B[128][6];
    int tid = threadIdx.x;
    for (int i = tid; i < 128 * 6; i += 256) {
        int k = i / 6, c = i % 6;
        B[k][c] = (c < 3) ? Wls[k * 3 + c] : Wln[k * 3 + (c - 3)];
    }
    __syncthreads();
    int gw = (blockIdx.x * 256 + tid) >> 5;
    int lane = tid & 31;
    if (gw >= NN) return;
    int n = gw;
    float p0 = 0.f, p1 = 0.f, p2 = 0.f, p3 = 0.f, p4 = 0.f, p5 = 0.f;
    for (int k = lane; k < 128; k += 32) {
        float f = g_feat[(size_t)n * 128 + k];
        p0 += f * B[k][0]; p1 += f * B[k][1]; p2 += f * B[k][2];
        p3 += f * B[k][3]; p4 += f * B[k][4]; p5 += f * B[k][5];
    }
#pragma unroll
    for (int o = 16; o > 0; o >>= 1) {
        p0 += __shfl_xor_sync(0xffffffff, p0, o);
        p1 += __shfl_xor_sync(0xffffffff, p1, o);
        p2 += __shfl_xor_sync(0xffffffff, p2, o);
        p3 += __shfl_xor_sync(0xffffffff, p3, o);
        p4 += __shfl_xor_sync(0xffffffff, p4, o);
        p5 += __shfl_xor_sync(0xffffffff, p5, o);
    }
    if (lane == 0) {
        g_t[(size_t)n * 6 + 0] = p0;
        g_t[(size_t)n * 6 + 1] = p1;
        g_t[(size_t)n * 6 + 2] = p2;
        g_t[(size_t)n * 6 + 3] = p3;
        g_t[(size_t)n * 6 + 4] = p4;
        g_t[(size_t)n * 6 + 5] = p5;
    }
}

__global__ void final_combine_kernel(const float* __restrict__ bl,
                                     float* __restrict__ out) {
    int n = blockIdx.x * blockDim.x + threadIdx.x;
    if (n >= NN) return;
    int s0 = g_off[n], s1 = g_off[n + 1];
    float a0 = 0.f, a1 = 0.f, a2 = 0.f;
    for (int e = s0; e < s1; e++) {
        int s = g_csr[e];
        a0 += g_t[(size_t)s * 6 + 3];
        a1 += g_t[(size_t)s * 6 + 4];
        a2 += g_t[(size_t)s * 6 + 5];
    }
    float inv = 1.0f / (float)max(s1 - s0, 1);
    out[n * 3 + 0] = g_t[(size_t)n * 6 + 0] + a0 * inv + bl[0];
    out[n * 3 + 1] = g_t[(size_t)n * 6 + 1] + a1 * inv + bl[1];
    out[n * 3 + 2] = g_t[(size_t)n * 6 + 2] + a2 * inv + bl[2];
}

// ---------------- launch ----------------
extern "C" void kernel_launch(void* const* d_in, const int* in_sizes, int n_in,
                              void* d_out, int out_size) {
    const float* vert = (const float*)d_in[0];
    const void*  edges = d_in[1];
    const float* vpot = (const float*)d_in[2];
    const float* z    = (const float*)d_in[3];
    const float* W0s  = (const float*)d_in[4];
    const float* W0n  = (const float*)d_in[5];
    const float* b0   = (const float*)d_in[6];
    const float* Wbs  = (const float*)d_in[7];
    const float* Wbn  = (const float*)d_in[8];
    const float* bb   = (const float*)d_in[9];
    const float* Wls  = (const float*)d_in[10];
    const float* Wln  = (const float*)d_in[11];
    const float* bl   = (const float*)d_in[12];
    float* out = (float*)d_out;

    cudaFuncSetAttribute(tc_gemm_kernel, cudaFuncAttributeMaxDynamicSharedMemorySize, GEMM_SMEM);

    // CSR build
    detect_kernel<<<1, 32>>>(edges);
    zero_counts_kernel<<<(NN + 1023) / 1024, 1024>>>();
    count_kernel<<<(EE + 255) / 256, 256>>>(edges);
    scan_block_kernel<<<SCAN_BLOCKS, 1024>>>();
    scan_tops_kernel<<<1, 128>>>();
    scan_add_kernel<<<SCAN_BLOCKS, 1024>>>();
    scatter_kernel<<<(EE + 255) / 256, 256>>>(edges);

    // weight split + A pad zero
    wconv_kernel<<<1024, 256>>>(Wbs, Wbn);
    zero_pad_kernel<<<(int)(((long long)NN * 10 + 255) / 256), 256>>>();

    // layer 0
    l0_gemm_kernel<<<NN / 32, 256>>>(vert, vpot, W0s, W0n);
    combine_body_kernel<<<(NN * 32 + 255) / 256, 256>>>(b0, z, vert, vpot);

    // 4 body layers
    for (int i = 0; i < 4; i++) {
        tc_gemm_kernel<<<MTILES, 256, GEMM_SMEM>>>(i);
        if (i < 3)
            combine_body_kernel<<<(NN * 32 + 255) / 256, 256>>>(
                bb + i * HH, z + (size_t)(i + 1) * NN * ZZ, vert, vpot);
        else
            combine_head_kernel<<<(NN * 32 + 255) / 256, 256>>>(bb + 3 * HH);
    }

    // head
    final_gemm_kernel<<<(NN * 32 + 255) / 256, 256>>>(Wls, Wln);
    final_combine_kernel<<<(NN + 255) / 256, 256>>>(bl, out);
}